// round 1
// baseline (speedup 1.0000x reference)
#include <cuda_runtime.h>
#include <math_constants.h>

// Problem shape (fixed by reference setup_inputs)
constexpr int BS  = 128;
constexpr int SEQ = 4096;
constexpr int HID = 128;

constexpr int WARPS   = 16;
constexpr int THREADS = WARPS * 32;          // 512
constexpr int ROWS_PER_WARP = SEQ / WARPS;   // 256

// One CTA per batch element. Flash-decode style single pass over encoder rows:
//  - each warp owns a contiguous 256-row slice of seq
//  - per row: lane loads float4 of enc row (32 lanes * 4 = 128 = HID),
//    dot with dec (held in registers), butterfly reduce -> score
//  - online softmax (running max m, running denom l) + rescaled context accum
//    using the SAME enc float4 already in registers (single HBM pass)
//  - raw scores parked in smem; after cross-warp combine the CTA normalizes
//    them in-place and writes attn_prob + context.
__global__ __launch_bounds__(THREADS, 1)
void seq2seq_attn_kernel(const float* __restrict__ dec,
                         const float* __restrict__ enc,
                         float* __restrict__ attn,   // [BS, SEQ]
                         float* __restrict__ ctx)    // [BS, HID]
{
    __shared__ float s_scores[SEQ];                 // 16 KB raw scores
    __shared__ float s_m[WARPS];
    __shared__ float s_l[WARPS];
    __shared__ float s_acc[WARPS][HID];             // 8 KB partial contexts

    const int b    = blockIdx.x;
    const int tid  = threadIdx.x;
    const int w    = tid >> 5;
    const int lane = tid & 31;

    // dec row: lane holds 4 contiguous components
    const float4 d = *reinterpret_cast<const float4*>(dec + (size_t)b * HID + lane * 4);

    const float* enc_b = enc + (size_t)b * SEQ * HID;

    float m = -CUDART_INF_F;
    float l = 0.0f;
    float4 acc = make_float4(0.f, 0.f, 0.f, 0.f);

    const int row0 = w * ROWS_PER_WARP;
    const int row1 = row0 + ROWS_PER_WARP;

    for (int r = row0; r < row1; r += 4) {
        float4 e0 = *reinterpret_cast<const float4*>(enc_b + (size_t)(r + 0) * HID + lane * 4);
        float4 e1 = *reinterpret_cast<const float4*>(enc_b + (size_t)(r + 1) * HID + lane * 4);
        float4 e2 = *reinterpret_cast<const float4*>(enc_b + (size_t)(r + 2) * HID + lane * 4);
        float4 e3 = *reinterpret_cast<const float4*>(enc_b + (size_t)(r + 3) * HID + lane * 4);

        float sc0 = e0.x * d.x + e0.y * d.y + e0.z * d.z + e0.w * d.w;
        float sc1 = e1.x * d.x + e1.y * d.y + e1.z * d.z + e1.w * d.w;
        float sc2 = e2.x * d.x + e2.y * d.y + e2.z * d.z + e2.w * d.w;
        float sc3 = e3.x * d.x + e3.y * d.y + e3.z * d.z + e3.w * d.w;

        // four independent butterfly reduces, interleaved for ILP
        #pragma unroll
        for (int off = 16; off >= 1; off >>= 1) {
            sc0 += __shfl_xor_sync(0xFFFFFFFFu, sc0, off);
            sc1 += __shfl_xor_sync(0xFFFFFFFFu, sc1, off);
            sc2 += __shfl_xor_sync(0xFFFFFFFFu, sc2, off);
            sc3 += __shfl_xor_sync(0xFFFFFFFFu, sc3, off);
        }

        // park raw scores (lane 0..3 each store one; avoids dynamic indexing)
        if (lane == 0) {
            s_scores[r + 0] = sc0;
            s_scores[r + 1] = sc1;
            s_scores[r + 2] = sc2;
            s_scores[r + 3] = sc3;
        }

        // online softmax update (batched over 4 rows)
        float mnew = fmaxf(fmaxf(fmaxf(sc0, sc1), fmaxf(sc2, sc3)), m);
        float scale = __expf(m - mnew);           // exp(-inf)=0 handles first iter
        float p0 = __expf(sc0 - mnew);
        float p1 = __expf(sc1 - mnew);
        float p2 = __expf(sc2 - mnew);
        float p3 = __expf(sc3 - mnew);
        l = l * scale + (p0 + p1) + (p2 + p3);

        acc.x = acc.x * scale + p0 * e0.x + p1 * e1.x + p2 * e2.x + p3 * e3.x;
        acc.y = acc.y * scale + p0 * e0.y + p1 * e1.y + p2 * e2.y + p3 * e3.y;
        acc.z = acc.z * scale + p0 * e0.z + p1 * e1.z + p2 * e2.z + p3 * e3.z;
        acc.w = acc.w * scale + p0 * e0.w + p1 * e1.w + p2 * e2.w + p3 * e3.w;

        m = mnew;
    }

    // per-warp results to smem
    if (lane == 0) { s_m[w] = m; s_l[w] = l; }
    *reinterpret_cast<float4*>(&s_acc[w][lane * 4]) = acc;
    __syncthreads();

    // every thread redundantly computes global max + denom (cheap: 16 iters)
    float M = -CUDART_INF_F;
    #pragma unroll
    for (int i = 0; i < WARPS; ++i) M = fmaxf(M, s_m[i]);
    float L = 0.0f;
    #pragma unroll
    for (int i = 0; i < WARPS; ++i) L += s_l[i] * __expf(s_m[i] - M);
    const float invL = 1.0f / L;

    // context: threads 0..127 each own one hidden component
    if (tid < HID) {
        float c = 0.0f;
        #pragma unroll
        for (int i = 0; i < WARPS; ++i) c += s_acc[i][tid] * __expf(s_m[i] - M);
        ctx[(size_t)b * HID + tid] = c * invL;
    }

    // attn_prob: normalize parked scores and stream out
    for (int idx = tid; idx < SEQ; idx += THREADS) {
        attn[(size_t)b * SEQ + idx] = __expf(s_scores[idx] - M) * invL;
    }
}

extern "C" void kernel_launch(void* const* d_in, const int* in_sizes, int n_in,
                              void* d_out, int out_size)
{
    // metadata order: decoder_state_t [BS,HID], encoder_states [BS,SEQ,HID].
    // Pick by size to be robust.
    const float* dec = (const float*)d_in[0];
    const float* enc = (const float*)d_in[1];
    if (n_in >= 2 && in_sizes[0] > in_sizes[1]) {
        dec = (const float*)d_in[1];
        enc = (const float*)d_in[0];
    }

    float* attn = (float*)d_out;                   // [BS, SEQ]
    float* ctx  = attn + (size_t)BS * SEQ;         // [BS, HID]

    seq2seq_attn_kernel<<<BS, THREADS>>>(dec, enc, attn, ctx);
}

// round 2
// speedup vs baseline: 1.1258x; 1.1258x over previous
#include <cuda_runtime.h>
#include <math_constants.h>

// Problem shape (fixed by reference setup_inputs)
constexpr int BS  = 128;
constexpr int SEQ = 4096;
constexpr int HID = 128;

constexpr int SPLIT = 2;                       // seq splits per batch
constexpr int ROWS_PER_CTA  = SEQ / SPLIT;     // 2048
constexpr int WARPS   = 16;
constexpr int THREADS = WARPS * 32;            // 512
constexpr int ROWS_PER_WARP = ROWS_PER_CTA / WARPS; // 128

// Split-softmax scratch (device globals: no allocation allowed)
__device__ float g_part_m[BS * SPLIT];
__device__ float g_part_l[BS * SPLIT];
__device__ float g_part_acc[BS * SPLIT * HID];

// Pass 1: each CTA handles one (batch, seq-half). Flash-decode single pass:
// raw scores -> smem (streamed out raw to attn buffer), online-softmax partial
// (m, l, acc[HID]) -> global scratch.
__global__ __launch_bounds__(THREADS, 2)
void attn_pass1(const float* __restrict__ dec,
                const float* __restrict__ enc,
                float* __restrict__ attn_raw)     // [BS, SEQ] raw scores
{
    __shared__ float s_scores[ROWS_PER_CTA];      // 8 KB
    __shared__ float s_m[WARPS];
    __shared__ float s_l[WARPS];
    __shared__ float s_acc[WARPS][HID];           // 8 KB

    const int b    = blockIdx.x;
    const int h    = blockIdx.y;                  // seq half
    const int tid  = threadIdx.x;
    const int w    = tid >> 5;
    const int lane = tid & 31;

    const float4 d = *reinterpret_cast<const float4*>(dec + (size_t)b * HID + lane * 4);

    const float* enc_b = enc + (size_t)b * SEQ * HID + (size_t)h * ROWS_PER_CTA * HID;

    float m = -CUDART_INF_F;
    float l = 0.0f;
    float4 acc = make_float4(0.f, 0.f, 0.f, 0.f);

    const int row0 = w * ROWS_PER_WARP;
    const int row1 = row0 + ROWS_PER_WARP;

    for (int r = row0; r < row1; r += 4) {
        float4 e0 = *reinterpret_cast<const float4*>(enc_b + (size_t)(r + 0) * HID + lane * 4);
        float4 e1 = *reinterpret_cast<const float4*>(enc_b + (size_t)(r + 1) * HID + lane * 4);
        float4 e2 = *reinterpret_cast<const float4*>(enc_b + (size_t)(r + 2) * HID + lane * 4);
        float4 e3 = *reinterpret_cast<const float4*>(enc_b + (size_t)(r + 3) * HID + lane * 4);

        float sc0 = e0.x * d.x + e0.y * d.y + e0.z * d.z + e0.w * d.w;
        float sc1 = e1.x * d.x + e1.y * d.y + e1.z * d.z + e1.w * d.w;
        float sc2 = e2.x * d.x + e2.y * d.y + e2.z * d.z + e2.w * d.w;
        float sc3 = e3.x * d.x + e3.y * d.y + e3.z * d.z + e3.w * d.w;

        #pragma unroll
        for (int off = 16; off >= 1; off >>= 1) {
            sc0 += __shfl_xor_sync(0xFFFFFFFFu, sc0, off);
            sc1 += __shfl_xor_sync(0xFFFFFFFFu, sc1, off);
            sc2 += __shfl_xor_sync(0xFFFFFFFFu, sc2, off);
            sc3 += __shfl_xor_sync(0xFFFFFFFFu, sc3, off);
        }

        if (lane == 0) {
            s_scores[r + 0] = sc0;
            s_scores[r + 1] = sc1;
            s_scores[r + 2] = sc2;
            s_scores[r + 3] = sc3;
        }

        float mnew = fmaxf(fmaxf(fmaxf(sc0, sc1), fmaxf(sc2, sc3)), m);
        float scale = __expf(m - mnew);           // exp(-inf)=0 on first iter
        float p0 = __expf(sc0 - mnew);
        float p1 = __expf(sc1 - mnew);
        float p2 = __expf(sc2 - mnew);
        float p3 = __expf(sc3 - mnew);
        l = l * scale + (p0 + p1) + (p2 + p3);

        acc.x = acc.x * scale + p0 * e0.x + p1 * e1.x + p2 * e2.x + p3 * e3.x;
        acc.y = acc.y * scale + p0 * e0.y + p1 * e1.y + p2 * e2.y + p3 * e3.y;
        acc.z = acc.z * scale + p0 * e0.z + p1 * e1.z + p2 * e2.z + p3 * e3.z;
        acc.w = acc.w * scale + p0 * e0.w + p1 * e1.w + p2 * e2.w + p3 * e3.w;

        m = mnew;
    }

    if (lane == 0) { s_m[w] = m; s_l[w] = l; }
    *reinterpret_cast<float4*>(&s_acc[w][lane * 4]) = acc;
    __syncthreads();

    // combine 16 warp partials -> CTA partial (redundant per thread, cheap)
    float M = -CUDART_INF_F;
    #pragma unroll
    for (int i = 0; i < WARPS; ++i) M = fmaxf(M, s_m[i]);
    float L = 0.0f;
    #pragma unroll
    for (int i = 0; i < WARPS; ++i) L += s_l[i] * __expf(s_m[i] - M);

    const int part = b * SPLIT + h;
    if (tid == 0) { g_part_m[part] = M; g_part_l[part] = L; }
    if (tid < HID) {
        float c = 0.0f;
        #pragma unroll
        for (int i = 0; i < WARPS; ++i) c += s_acc[i][tid] * __expf(s_m[i] - M);
        g_part_acc[(size_t)part * HID + tid] = c;   // unnormalized, max M
    }

    // stream raw scores to gmem (coalesced); pass 2 normalizes (hits L2)
    float* out = attn_raw + (size_t)b * SEQ + (size_t)h * ROWS_PER_CTA;
    for (int idx = tid; idx < ROWS_PER_CTA; idx += THREADS) {
        out[idx] = s_scores[idx];
    }
}

// Pass 2: one CTA per batch — combine the SPLIT partials, normalize raw
// scores in place, write context.
__global__ __launch_bounds__(THREADS, 2)
void attn_pass2(float* __restrict__ attn,         // [BS, SEQ] raw in, prob out
                float* __restrict__ ctx)          // [BS, HID]
{
    const int b   = blockIdx.x;
    const int tid = threadIdx.x;

    float pm[SPLIT], pl[SPLIT];
    #pragma unroll
    for (int i = 0; i < SPLIT; ++i) {
        pm[i] = g_part_m[b * SPLIT + i];
        pl[i] = g_part_l[b * SPLIT + i];
    }
    float M = pm[0];
    #pragma unroll
    for (int i = 1; i < SPLIT; ++i) M = fmaxf(M, pm[i]);
    float L = 0.0f;
    #pragma unroll
    for (int i = 0; i < SPLIT; ++i) L += pl[i] * __expf(pm[i] - M);
    const float invL = 1.0f / L;

    if (tid < HID) {
        float c = 0.0f;
        #pragma unroll
        for (int i = 0; i < SPLIT; ++i)
            c += g_part_acc[(size_t)(b * SPLIT + i) * HID + tid] * __expf(pm[i] - M);
        ctx[(size_t)b * HID + tid] = c * invL;
    }

    float* a = attn + (size_t)b * SEQ;
    #pragma unroll 4
    for (int idx = tid; idx < SEQ; idx += THREADS) {
        a[idx] = __expf(a[idx] - M) * invL;
    }
}

extern "C" void kernel_launch(void* const* d_in, const int* in_sizes, int n_in,
                              void* d_out, int out_size)
{
    const float* dec = (const float*)d_in[0];
    const float* enc = (const float*)d_in[1];
    if (n_in >= 2 && in_sizes[0] > in_sizes[1]) {
        dec = (const float*)d_in[1];
        enc = (const float*)d_in[0];
    }

    float* attn = (float*)d_out;                   // [BS, SEQ]
    float* ctx  = attn + (size_t)BS * SEQ;         // [BS, HID]

    attn_pass1<<<dim3(BS, SPLIT), THREADS>>>(dec, enc, attn);
    attn_pass2<<<BS, THREADS>>>(attn, ctx);
}